// round 13
// baseline (speedup 1.0000x reference)
#include <cuda_runtime.h>
#include <cuda_bf16.h>
#include <stdint.h>

#define S_DIM 128
#define NB    32          // batch -> MMA N
#define E_DIM 512
#define F_DIM 2048
#define KT    32          // K per chunk
#define MT    128         // M tile
#define LN_EPS 1e-5f

// ---------------- scratch (static device mem: allocation-guard-safe) --------
__device__ __align__(16) __nv_bfloat16 g_hh[(size_t)S_DIM * NB * F_DIM];   // h hi [s][b][f]
__device__ __align__(16) __nv_bfloat16 g_hl[(size_t)S_DIM * NB * F_DIM];   // h lo [s][b][f]
__device__ __align__(16) float         g_outt[(size_t)S_DIM * E_DIM * NB]; // y^T [s][e][b]

// ---------------- dynamic smem layout (bytes) -------------------------------
// A bf16 tiles:  2 bufs x (hi[32][136] + lo) = 34816   (R6-validated layout)
// B stages:      GEMM1 fp32 3 x [32][36]f    = 13824 @ 34816
//                GEMM2 bf16 3 x (hi+lo 5120) = 15360 @ 34816
// B mma (GEMM1): 2 x 5120                    = 10240 @ 48640
// epilogue unions overlay at offset 0 (c_nm 16896 B / c_mn 18432 B)
#define ACV_OFF    0
#define ACV_BUF    17408
#define ACV_LO     8704
#define B_ST_OFF   34816
#define B_F32_SZ   4608
#define B_BF_SZ    5120
#define BMMA_OFF   48640
#define SMEM_BYTES 58880

// ---------------- helpers ---------------------------------------------------
__device__ __forceinline__ uint32_t sptr(const void* p) {
    return (uint32_t)__cvta_generic_to_shared(p);
}
__device__ __forceinline__ void cp_async16(void* smemp, const void* gmem) {
    asm volatile("cp.async.cg.shared.global [%0], [%1], 16;\n"
                 :: "r"(sptr(smemp)), "l"(gmem));
}
__device__ __forceinline__ void cp_commit() { asm volatile("cp.async.commit_group;\n"); }
__device__ __forceinline__ void cp_wait1()  { asm volatile("cp.async.wait_group 1;\n"); }

__device__ __forceinline__ void ldsm_x4(uint32_t* r, uint32_t a) {
    asm volatile("ldmatrix.sync.aligned.m8n8.x4.shared.b16 {%0,%1,%2,%3}, [%4];"
                 : "=r"(r[0]), "=r"(r[1]), "=r"(r[2]), "=r"(r[3]) : "r"(a));
}
__device__ __forceinline__ void ldsm_x4t(uint32_t* r, uint32_t a) {
    asm volatile("ldmatrix.sync.aligned.m8n8.x4.trans.shared.b16 {%0,%1,%2,%3}, [%4];"
                 : "=r"(r[0]), "=r"(r[1]), "=r"(r[2]), "=r"(r[3]) : "r"(a));
}
__device__ __forceinline__ void mma_bf16(float* d, const uint32_t* a, uint32_t b0, uint32_t b1) {
    asm volatile("mma.sync.aligned.m16n8k16.row.col.f32.bf16.bf16.f32 "
                 "{%0,%1,%2,%3}, {%4,%5,%6,%7}, {%8,%9}, {%0,%1,%2,%3};"
                 : "+f"(d[0]), "+f"(d[1]), "+f"(d[2]), "+f"(d[3])
                 : "r"(a[0]), "r"(a[1]), "r"(a[2]), "r"(a[3]), "r"(b0), "r"(b1));
}
// split two fp32 into packed bf16x2 hi + lo
__device__ __forceinline__ void split2(float f0, float f1, uint32_t& hi, uint32_t& lo) {
    __nv_bfloat162 h = __floats2bfloat162_rn(f0, f1);
    float r0 = f0 - __bfloat162float(h.x);
    float r1 = f1 - __bfloat162float(h.y);
    __nv_bfloat162 l = __floats2bfloat162_rn(r0, r1);
    hi = *reinterpret_cast<uint32_t*>(&h);
    lo = *reinterpret_cast<uint32_t*>(&l);
}

// ----------------------------------------------------------------------------
// Warp-MMA batched-per-s GEMM, bf16 hi/lo 3-pass fp32 emulation.
//   D[m, n] = sum_k W[s, k, m0+m] * Bact[n, k]   (m tile 128, n = 32 batch)
// A path: 2-deep register-prefetched LDG -> split -> STS bf16 (NO fp32 smem
// stage). B path: cp.async ring as in R11 (validated).
// Per chunk: wait1 -> STS A(regs) -> ldgA(c+2) -> convert B -> bar
//            -> issueB(c+2) -> MMA(c)
// ----------------------------------------------------------------------------
template<int K_TOT, int M_TOT, bool B_BF16, bool EPI2>
__global__ __launch_bounds__(256, 2)
void ffn_mma(const float* __restrict__ W, const float* __restrict__ Xf,
             const __nv_bfloat16* __restrict__ Bh_g, const __nv_bfloat16* __restrict__ Bl_g,
             const float* __restrict__ bias,
             __nv_bfloat16* __restrict__ Hh, __nv_bfloat16* __restrict__ Hl,
             float* __restrict__ OutT)
{
    constexpr int NC = K_TOT / KT;
    extern __shared__ __align__(16) char smem[];

    const int s    = blockIdx.y;
    const int m0   = blockIdx.x * MT;
    const int tid  = threadIdx.x;
    const int lane = tid & 31;
    const int warp = tid >> 5;

    // ---- A register staging: rows (tid>>5)+8i, float cols (tid&31)*4 ----
    const int ar0 = tid >> 5;
    const int acc4 = tid & 31;
    const float* Abase = W + ((size_t)s * K_TOT + ar0) * M_TOT + m0 + acc4 * 4;

    float4 rA[2][4];
    auto ldgA = [&](int c, int buf) {
        if (c < NC) {
            const float* ap = Abase + (size_t)c * KT * M_TOT;
            #pragma unroll
            for (int i = 0; i < 4; i++)
                rA[buf][i] = *(const float4*)(ap + (size_t)(8 * i) * M_TOT);
        }
    };

    // ---- B cp.async ring (one group per call) ----
    auto issueB = [&](int c) {
        if (c < NC) {
            const int st = c % 3;
            if (!B_BF16) {
                const int b = tid >> 3, col = tid & 7;
                float* bd = (float*)(smem + B_ST_OFF + st * B_F32_SZ);
                cp_async16(bd + b * 36 + col * 4,
                           Xf + ((size_t)b * S_DIM + s) * K_TOT + (size_t)c * KT + col * 4);
            } else {
                const int sel = tid >> 7;                   // 0 hi, 1 lo
                const int r = (tid & 127) >> 2, cc = tid & 3;
                const __nv_bfloat16* src = (sel ? Bl_g : Bh_g)
                    + ((size_t)s * NB + r) * K_TOT + (size_t)c * KT + cc * 8;
                char* bd = smem + B_ST_OFF + st * B_BF_SZ + sel * 2560;
                cp_async16(bd + r * 80 + cc * 16, src);
            }
        }
        cp_commit();
    };

    // ---- ldmatrix lane addressing (R6-validated) ----
    const int a_kr = (lane & 7) + ((lane >> 4) << 3);          // k row in 16-chunk
    const int a_mc = warp * 16 + (((lane >> 3) & 1) << 3);     // m col
    const int b_nr = (lane & 7) + (((lane >> 3) & 1) << 3);    // n row in 16-chunk
    const int b_kc = (lane >> 4) << 3;                         // k col

    float acc[4][4];
    #pragma unroll
    for (int j = 0; j < 4; j++)
        #pragma unroll
        for (int i = 0; i < 4; i++) acc[j][i] = 0.f;

    ldgA(0, 0); ldgA(1, 1);
    issueB(0); issueB(1);

    for (int c = 0; c < NC; c++) {
        cp_wait1();                       // this thread's B group <= c complete

        // ---- A: split regs -> STS bf16 hi/lo into ACV buf c&1 ----
        {
            char* dh = smem + ACV_OFF + (c & 1) * ACV_BUF;
            #pragma unroll
            for (int i = 0; i < 4; i++) {
                const int r = ar0 + i * 8;
                float4 v = rA[c & 1][i];
                uint32_t h0, l0, h1, l1;
                split2(v.x, v.y, h0, l0);
                split2(v.z, v.w, h1, l1);
                *(uint2*)(dh + r * 272 + acc4 * 8)          = make_uint2(h0, h1);
                *(uint2*)(dh + ACV_LO + r * 272 + acc4 * 8) = make_uint2(l0, l1);
            }
        }
        ldgA(c + 2, c & 1);               // refill consumed reg buffer

        if (!B_BF16) {
            // OWNER-convert B: thread wrote row tid>>3, float cols (tid&7)*4
            const int b = tid >> 3, cc = tid & 7;
            const float* bs = (const float*)(smem + B_ST_OFF + (c % 3) * B_F32_SZ)
                              + b * 36 + cc * 4;
            float4 v = *(const float4*)bs;
            uint32_t h0, l0, h1, l1;
            split2(v.x, v.y, h0, l0);
            split2(v.z, v.w, h1, l1);
            char* dh = smem + BMMA_OFF + (c & 1) * 5120 + b * 80 + cc * 8;
            *(uint2*)dh          = make_uint2(h0, h1);
            *(uint2*)(dh + 2560) = make_uint2(l0, l1);
        }
        __syncthreads();                  // publish STS + B stage c; fence MMA(c-1)
        issueB(c + 2);

        // ---- MMA on chunk c (R6-validated ldsm path) ----
        const char* ahb = smem + ACV_OFF + (c & 1) * ACV_BUF;
        const char* bbp = B_BF16 ? smem + B_ST_OFF + (c % 3) * B_BF_SZ
                                 : smem + BMMA_OFF + (c & 1) * 5120;
        #pragma unroll
        for (int kh = 0; kh < 2; kh++) {
            uint32_t ah[4], al[4], bh[8], bl[8];
            const uint32_t aro = (uint32_t)((kh * 16 + a_kr) * 272 + a_mc * 2);
            ldsm_x4t(ah, sptr(ahb) + aro);
            ldsm_x4t(al, sptr(ahb) + ACV_LO + aro);
            #pragma unroll
            for (int q = 0; q < 2; q++) {
                const uint32_t ro = (uint32_t)((q * 16 + b_nr) * 80 + (kh * 16 + b_kc) * 2);
                ldsm_x4(bh + 4 * q, sptr(bbp) + ro);
                ldsm_x4(bl + 4 * q, sptr(bbp) + 2560 + ro);
            }
            #pragma unroll
            for (int j = 0; j < 4; j++) {
                const int q = (j >> 1) * 4 + (j & 1);
                mma_bf16(acc[j], ah, bh[q], bh[q + 2]);
                mma_bf16(acc[j], ah, bl[q], bl[q + 2]);
                mma_bf16(acc[j], al, bh[q], bh[q + 2]);
            }
        }
    }
    __syncthreads();                      // all MMAs done before smem reuse

    // ---- epilogue (R6-validated) ----
    if (!EPI2) {
        float (*c_nm)[132] = (float(*)[132])smem;
        #pragma unroll
        for (int j = 0; j < 4; j++) {
            const int n = j * 8 + (lane & 3) * 2;
            const int m = warp * 16 + (lane >> 2);
            c_nm[n][m]         = acc[j][0];
            c_nm[n + 1][m]     = acc[j][1];
            c_nm[n][m + 8]     = acc[j][2];
            c_nm[n + 1][m + 8] = acc[j][3];
        }
        __syncthreads();
        const int n  = tid >> 3;
        const int fo = (tid & 7) * 16;
        const float* bp = bias + (size_t)s * M_TOT + m0 + fo;
        uint32_t hi[8], lo[8];
        #pragma unroll
        for (int q = 0; q < 4; q++) {
            float4 v = *(const float4*)&c_nm[n][fo + q * 4];
            v.x += bp[q * 4]; v.y += bp[q * 4 + 1]; v.z += bp[q * 4 + 2]; v.w += bp[q * 4 + 3];
            split2(v.x, v.y, hi[2 * q], lo[2 * q]);
            split2(v.z, v.w, hi[2 * q + 1], lo[2 * q + 1]);
        }
        const size_t o = ((size_t)s * NB + n) * (size_t)M_TOT + m0 + fo;
        ((uint4*)(Hh + o))[0] = make_uint4(hi[0], hi[1], hi[2], hi[3]);
        ((uint4*)(Hh + o))[1] = make_uint4(hi[4], hi[5], hi[6], hi[7]);
        ((uint4*)(Hl + o))[0] = make_uint4(lo[0], lo[1], lo[2], lo[3]);
        ((uint4*)(Hl + o))[1] = make_uint4(lo[4], lo[5], lo[6], lo[7]);
    } else {
        float (*c_mn)[36] = (float(*)[36])smem;
        #pragma unroll
        for (int j = 0; j < 4; j++) {
            const int n = j * 8 + (lane & 3) * 2;
            const int m = warp * 16 + (lane >> 2);
            c_mn[m][n]         = acc[j][0];
            c_mn[m][n + 1]     = acc[j][1];
            c_mn[m + 8][n]     = acc[j][2];
            c_mn[m + 8][n + 1] = acc[j][3];
        }
        __syncthreads();
        const int e  = tid >> 1;
        const int bo = (tid & 1) * 16;
        const float bv = bias[(size_t)s * M_TOT + m0 + e];
        float* dst = OutT + ((size_t)s * M_TOT + m0 + e) * NB + bo;
        #pragma unroll
        for (int q = 0; q < 4; q++) {
            float4 v = *(const float4*)&c_mn[e][bo + q * 4];
            ((float4*)dst)[q] = make_float4(v.x + bv, v.y + bv, v.z + bv, v.w + bv);
        }
    }
}

// ----------------------------------------------------------------------------
// LayerNorm: y = y^T + x (residual), normalize over e, write [b][s][e].
// ----------------------------------------------------------------------------
__global__ __launch_bounds__(256)
void ln_kernel(const float* __restrict__ OutT, const float* __restrict__ x,
               const float* __restrict__ gamma, const float* __restrict__ beta,
               float* __restrict__ out)
{
    extern __shared__ float ys[];                 // [E_DIM][33]
    __shared__ float ps[8][NB], pq[8][NB], mu_s[NB], inv_s[NB];
    const int s = blockIdx.x, tid = threadIdx.x, lane = tid & 31, w = tid >> 5;

    #pragma unroll
    for (int bi = 0; bi < 4; bi++) {
        const int b = w * 4 + bi;
        const float* xp = x + ((size_t)b * S_DIM + s) * E_DIM;
        for (int e = lane; e < E_DIM; e += 32) ys[e * 33 + b] = xp[e];
    }
    __syncthreads();

    float sum = 0.f, sq = 0.f;
    const float* op = OutT + (size_t)s * E_DIM * NB;
    for (int e = w; e < E_DIM; e += 8) {
        float v = op[(size_t)e * NB + lane] + ys[e * 33 + lane];
        ys[e * 33 + lane] = v;
        sum += v; sq += v * v;
    }
    ps[w][lane] = sum; pq[w][lane] = sq;
    __syncthreads();

    if (tid < NB) {
        float ts = 0.f, tq = 0.f;
        #pragma unroll
        for (int i = 0; i < 8; i++) { ts += ps[i][tid]; tq += pq[i][tid]; }
        const float mu  = ts * (1.0f / E_DIM);
        const float var = tq * (1.0f / E_DIM) - mu * mu;
        mu_s[tid]  = mu;
        inv_s[tid] = rsqrtf(var + LN_EPS);
    }
    __syncthreads();

    #pragma unroll
    for (int bi = 0; bi < 4; bi++) {
        const int b = w * 4 + bi;
        const float mu = mu_s[b], inv = inv_s[b];
        float* dst = out + ((size_t)b * S_DIM + s) * E_DIM;
        for (int e = lane; e < E_DIM; e += 32)
            dst[e] = (ys[e * 33 + b] - mu) * inv * gamma[e] + beta[e];
    }
}

// ----------------------------------------------------------------------------
extern "C" void kernel_launch(void* const* d_in, const int* in_sizes, int n_in,
                              void* d_out, int out_size)
{
    const float* x     = (const float*)d_in[0];
    const float* W1    = (const float*)d_in[1];
    const float* b1    = (const float*)d_in[2];
    const float* W2    = (const float*)d_in[3];
    const float* b2    = (const float*)d_in[4];
    const float* gamma = (const float*)d_in[5];
    const float* beta  = (const float*)d_in[6];
    float* out = (float*)d_out;

    __nv_bfloat16 *hh, *hl;
    float* outt;
    cudaGetSymbolAddress((void**)&hh,   g_hh);
    cudaGetSymbolAddress((void**)&hl,   g_hl);
    cudaGetSymbolAddress((void**)&outt, g_outt);

    const int ln_smem = E_DIM * 33 * (int)sizeof(float);   // 67584 B
    cudaFuncSetAttribute(ln_kernel, cudaFuncAttributeMaxDynamicSharedMemorySize, ln_smem);
    cudaFuncSetAttribute(ffn_mma<E_DIM, F_DIM, false, false>,
                         cudaFuncAttributeMaxDynamicSharedMemorySize, SMEM_BYTES);
    cudaFuncSetAttribute(ffn_mma<F_DIM, E_DIM, true, true>,
                         cudaFuncAttributeMaxDynamicSharedMemorySize, SMEM_BYTES);

    // GEMM1: h = x @ W1 + b1 -> bf16 hi/lo scratch   (M=F, K=E)
    ffn_mma<E_DIM, F_DIM, false, false><<<dim3(F_DIM / MT, S_DIM), 256, SMEM_BYTES>>>(
        W1, x, nullptr, nullptr, b1, hh, hl, nullptr);
    // GEMM2: y^T = h @ W2 + b2 -> fp32 scratch       (M=E, K=F)
    ffn_mma<F_DIM, E_DIM, true, true><<<dim3(E_DIM / MT, S_DIM), 256, SMEM_BYTES>>>(
        W2, nullptr, hh, hl, b2, nullptr, nullptr, outt);
    // LN(+residual) -> out [b][s][e]
    ln_kernel<<<S_DIM, 256, ln_smem>>>(outt, x, gamma, beta, out);
}

// round 14
// speedup vs baseline: 1.2332x; 1.2332x over previous
#include <cuda_runtime.h>
#include <cuda_bf16.h>
#include <stdint.h>

#define S_DIM 128
#define NB    32          // batch -> MMA N
#define E_DIM 512
#define F_DIM 2048
#define KT    16          // K per chunk
#define MT    256         // M tile (2 m16 tiles per warp)
#define LN_EPS 1e-5f

// ---------------- scratch (static device mem: allocation-guard-safe) --------
__device__ __align__(16) __nv_bfloat16 g_hh[(size_t)S_DIM * NB * F_DIM];   // h hi [s][b][f]
__device__ __align__(16) __nv_bfloat16 g_hl[(size_t)S_DIM * NB * F_DIM];   // h lo [s][b][f]
__device__ __align__(16) float         g_outt[(size_t)S_DIM * E_DIM * NB]; // y^T [s][e][b]

// ---------------- dynamic smem layout (bytes) -------------------------------
// A fp32 stages: 3 x [16][260]f = 3 x 16640 = 49920
// A bf16 tiles:  2 bufs x (hi 16x528B + lo)  = 33792   @ 49920
// B stages (ring 3): gemm1 fp32 32x20f=2560/st; gemm2 bf16 (hi 32x48 + lo)=3072/st
// B mma (gemm1): 2 x 3072 @ 92928
// epilogue unions overlay at offset 0 (c_nm 33792 B / c_mn 36864 B)
#define A_ST_OFF   0
#define A_ST_SZ    16640
#define ACV_OFF    49920
#define ACV_BUF    16896
#define ACV_LO     8448
#define B_ST_OFF   83712
#define BMMA_OFF   92928
#define SMEM_BYTES 99072

// ---------------- helpers ---------------------------------------------------
__device__ __forceinline__ uint32_t sptr(const void* p) {
    return (uint32_t)__cvta_generic_to_shared(p);
}
__device__ __forceinline__ void cp_async16(void* smemp, const void* gmem) {
    asm volatile("cp.async.cg.shared.global [%0], [%1], 16;\n"
                 :: "r"(sptr(smemp)), "l"(gmem));
}
__device__ __forceinline__ void cp_commit() { asm volatile("cp.async.commit_group;\n"); }
__device__ __forceinline__ void cp_wait1()  { asm volatile("cp.async.wait_group 1;\n"); }

__device__ __forceinline__ void ldsm_x4(uint32_t* r, uint32_t a) {
    asm volatile("ldmatrix.sync.aligned.m8n8.x4.shared.b16 {%0,%1,%2,%3}, [%4];"
                 : "=r"(r[0]), "=r"(r[1]), "=r"(r[2]), "=r"(r[3]) : "r"(a));
}
__device__ __forceinline__ void ldsm_x4t(uint32_t* r, uint32_t a) {
    asm volatile("ldmatrix.sync.aligned.m8n8.x4.trans.shared.b16 {%0,%1,%2,%3}, [%4];"
                 : "=r"(r[0]), "=r"(r[1]), "=r"(r[2]), "=r"(r[3]) : "r"(a));
}
__device__ __forceinline__ void mma_bf16(float* d, const uint32_t* a, uint32_t b0, uint32_t b1) {
    asm volatile("mma.sync.aligned.m16n8k16.row.col.f32.bf16.bf16.f32 "
                 "{%0,%1,%2,%3}, {%4,%5,%6,%7}, {%8,%9}, {%0,%1,%2,%3};"
                 : "+f"(d[0]), "+f"(d[1]), "+f"(d[2]), "+f"(d[3])
                 : "r"(a[0]), "r"(a[1]), "r"(a[2]), "r"(a[3]), "r"(b0), "r"(b1));
}
// split two fp32 into packed bf16x2 hi + lo
__device__ __forceinline__ void split2(float f0, float f1, uint32_t& hi, uint32_t& lo) {
    __nv_bfloat162 h = __floats2bfloat162_rn(f0, f1);
    float r0 = f0 - __bfloat162float(h.x);
    float r1 = f1 - __bfloat162float(h.y);
    __nv_bfloat162 l = __floats2bfloat162_rn(r0, r1);
    hi = *reinterpret_cast<uint32_t*>(&h);
    lo = *reinterpret_cast<uint32_t*>(&l);
}

// ----------------------------------------------------------------------------
// Warp-MMA batched-per-s GEMM, bf16 hi/lo 3-pass fp32 emulation.
//   D[m, n] = sum_k W[s, k, m0+m] * Bact[n, k]   (m tile 256, n = 32 batch)
// MT=256/KT=16: halves redundant B-ldsm traffic per W element (L1-bound fix).
// Pipeline per chunk (R12-validated ordering):
//   wait1 -> owner-convert A + B (own cp.async data) -> bar -> issue(c+2) -> MMA(c)
// ----------------------------------------------------------------------------
template<int K_TOT, int M_TOT, bool B_BF16, bool EPI2>
__global__ __launch_bounds__(256, 2)
void ffn_mma(const float* __restrict__ W, const float* __restrict__ Xf,
             const __nv_bfloat16* __restrict__ Bh_g, const __nv_bfloat16* __restrict__ Bl_g,
             const float* __restrict__ bias,
             __nv_bfloat16* __restrict__ Hh, __nv_bfloat16* __restrict__ Hl,
             float* __restrict__ OutT)
{
    constexpr int NC = K_TOT / KT;
    constexpr int B_STG = B_BF16 ? 3072 : 2560;    // bytes per B stage
    extern __shared__ __align__(16) char smem[];

    const int s    = blockIdx.y;
    const int m0   = blockIdx.x * MT;
    const int tid  = threadIdx.x;
    const int lane = tid & 31;
    const int warp = tid >> 5;

    // ---- stage issue: cp.async chunk c into stage c%3 (one group per call) ----
    auto issue = [&](int c) {
        if (c < NC) {
            const int st = c % 3;
            // A tile: 16 rows x 256 floats = 1024 x 16B, 4 per thread
            float* ad = (float*)(smem + A_ST_OFF + st * A_ST_SZ);
            const float* as = W + ((size_t)s * K_TOT + (size_t)c * KT) * M_TOT + m0;
            #pragma unroll
            for (int i = 0; i < 4; i++) {
                const int q   = tid + i * 256;
                const int row = q >> 6, col = q & 63;      // col in 16B units
                cp_async16(ad + row * 260 + col * 4,
                           as + (size_t)row * M_TOT + col * 4);
            }
            if (!B_BF16) {
                // B fp32: 32 rows x 16 floats = 128 x 16B (tid < 128)
                if (tid < 128) {
                    const int b = tid >> 2, cc = tid & 3;
                    float* bd = (float*)(smem + B_ST_OFF + st * B_STG);
                    cp_async16(bd + b * 20 + cc * 4,
                               Xf + ((size_t)b * S_DIM + s) * K_TOT + (size_t)c * KT + cc * 4);
                }
            } else {
                // B bf16 hi/lo: 32 rows x 2 x 16B each (tid < 128)
                if (tid < 128) {
                    const int sel = tid >> 6;               // 0 hi, 1 lo
                    const int r = (tid & 63) >> 1, cc = tid & 1;
                    const __nv_bfloat16* src = (sel ? Bl_g : Bh_g)
                        + ((size_t)s * NB + r) * K_TOT + (size_t)c * KT + cc * 8;
                    char* bd = smem + B_ST_OFF + st * B_STG + sel * 1536;
                    cp_async16(bd + r * 48 + cc * 16, src);
                }
            }
        }
        cp_commit();
    };

    // ---- ldmatrix lane addressing (R6-validated pattern) ----
    const int a_kr = (lane & 7) + ((lane >> 4) << 3);          // k row 0..15
    const int a_m8 = ((lane >> 3) & 1) << 3;                   // m col +0/+8
    const int b_nr = (lane & 7) + (((lane >> 3) & 1) << 3);    // n row in 16-chunk
    const int b_kc = (lane >> 4) << 3;                         // k col 0/8

    float acc[2][4][4];
    #pragma unroll
    for (int mi = 0; mi < 2; mi++)
        #pragma unroll
        for (int j = 0; j < 4; j++)
            #pragma unroll
            for (int i = 0; i < 4; i++) acc[mi][j][i] = 0.f;

    issue(0); issue(1);

    for (int c = 0; c < NC; c++) {
        cp_wait1();                       // this thread's group <= c complete

        // ---- OWNER-convert A: rows (tid>>6)+4i, float cols (tid&63)*4 ----
        {
            const float* ast = (const float*)(smem + A_ST_OFF + (c % 3) * A_ST_SZ);
            char* dh = smem + ACV_OFF + (c & 1) * ACV_BUF;
            const int cc = tid & 63;
            #pragma unroll
            for (int i = 0; i < 4; i++) {
                const int r = (tid >> 6) + 4 * i;
                float4 v = *(const float4*)(ast + r * 260 + cc * 4);
                uint32_t h0, l0, h1, l1;
                split2(v.x, v.y, h0, l0);
                split2(v.z, v.w, h1, l1);
                *(uint2*)(dh + r * 528 + cc * 8)          = make_uint2(h0, h1);
                *(uint2*)(dh + ACV_LO + r * 528 + cc * 8) = make_uint2(l0, l1);
            }
        }
        if (!B_BF16) {
            // OWNER-convert B: thread wrote row tid>>2, float cols (tid&3)*4
            if (tid < 128) {
                const int b = tid >> 2, cc = tid & 3;
                const float* bs = (const float*)(smem + B_ST_OFF + (c % 3) * B_STG)
                                  + b * 20 + cc * 4;
                float4 v = *(const float4*)bs;
                uint32_t h0, l0, h1, l1;
                split2(v.x, v.y, h0, l0);
                split2(v.z, v.w, h1, l1);
                char* dh = smem + BMMA_OFF + (c & 1) * 3072 + b * 48 + cc * 8;
                *(uint2*)dh          = make_uint2(h0, h1);
                *(uint2*)(dh + 1536) = make_uint2(l0, l1);
            }
        }
        __syncthreads();                  // publish converts + stage c; fence MMA(c-1)
        issue(c + 2);

        // ---- MMA on chunk c ----
        const char* ahb = smem + ACV_OFF + (c & 1) * ACV_BUF;
        const char* bbp = B_BF16 ? smem + B_ST_OFF + (c % 3) * B_STG
                                 : smem + BMMA_OFF + (c & 1) * 3072;
        uint32_t ah[2][4], al[2][4], bh[8], bl[8];
        #pragma unroll
        for (int mi = 0; mi < 2; mi++) {
            const uint32_t aro = (uint32_t)(a_kr * 528 + (warp * 32 + mi * 16 + a_m8) * 2);
            ldsm_x4t(ah[mi], sptr(ahb) + aro);
            ldsm_x4t(al[mi], sptr(ahb) + ACV_LO + aro);
        }
        #pragma unroll
        for (int q = 0; q < 2; q++) {
            const uint32_t ro = (uint32_t)((q * 16 + b_nr) * 48 + b_kc * 2);
            ldsm_x4(bh + 4 * q, sptr(bbp) + ro);
            ldsm_x4(bl + 4 * q, sptr(bbp) + 1536 + ro);
        }
        #pragma unroll
        for (int mi = 0; mi < 2; mi++)
            #pragma unroll
            for (int j = 0; j < 4; j++) {
                const int q = (j >> 1) * 4 + (j & 1);
                mma_bf16(acc[mi][j], ah[mi], bh[q], bh[q + 2]);
                mma_bf16(acc[mi][j], ah[mi], bl[q], bl[q + 2]);
                mma_bf16(acc[mi][j], al[mi], bh[q], bh[q + 2]);
            }
    }
    __syncthreads();                      // all MMAs done before smem reuse

    // ---- epilogue ----
    if (!EPI2) {
        float (*c_nm)[264] = (float(*)[264])smem;
        #pragma unroll
        for (int mi = 0; mi < 2; mi++)
            #pragma unroll
            for (int j = 0; j < 4; j++) {
                const int n = j * 8 + (lane & 3) * 2;
                const int m = warp * 32 + mi * 16 + (lane >> 2);
                c_nm[n][m]         = acc[mi][j][0];
                c_nm[n + 1][m]     = acc[mi][j][1];
                c_nm[n][m + 8]     = acc[mi][j][2];
                c_nm[n + 1][m + 8] = acc[mi][j][3];
            }
        __syncthreads();
        const int n  = tid >> 3;
        const int fo = (tid & 7) * 32;
        const float* bp = bias + (size_t)s * M_TOT + m0 + fo;
        uint32_t hi[16], lo[16];
        #pragma unroll
        for (int q = 0; q < 8; q++) {
            float4 v = *(const float4*)&c_nm[n][fo + q * 4];
            v.x += bp[q * 4]; v.y += bp[q * 4 + 1]; v.z += bp[q * 4 + 2]; v.w += bp[q * 4 + 3];
            split2(v.x, v.y, hi[2 * q], lo[2 * q]);
            split2(v.z, v.w, hi[2 * q + 1], lo[2 * q + 1]);
        }
        const size_t o = ((size_t)s * NB + n) * (size_t)M_TOT + m0 + fo;
        #pragma unroll
        for (int q = 0; q < 4; q++) {
            ((uint4*)(Hh + o))[q] = make_uint4(hi[4*q], hi[4*q+1], hi[4*q+2], hi[4*q+3]);
            ((uint4*)(Hl + o))[q] = make_uint4(lo[4*q], lo[4*q+1], lo[4*q+2], lo[4*q+3]);
        }
    } else {
        float (*c_mn)[36] = (float(*)[36])smem;
        #pragma unroll
        for (int mi = 0; mi < 2; mi++)
            #pragma unroll
            for (int j = 0; j < 4; j++) {
                const int n = j * 8 + (lane & 3) * 2;
                const int m = warp * 32 + mi * 16 + (lane >> 2);
                c_mn[m][n]         = acc[mi][j][0];
                c_mn[m][n + 1]     = acc[mi][j][1];
                c_mn[m + 8][n]     = acc[mi][j][2];
                c_mn[m + 8][n + 1] = acc[mi][j][3];
            }
        __syncthreads();
        const int e = tid;                               // 0..255
        const float bv = bias[(size_t)s * M_TOT + m0 + e];
        float* dst = OutT + ((size_t)s * M_TOT + m0 + e) * NB;
        #pragma unroll
        for (int q = 0; q < 8; q++) {
            float4 v = *(const float4*)&c_mn[e][q * 4];
            ((float4*)dst)[q] = make_float4(v.x + bv, v.y + bv, v.z + bv, v.w + bv);
        }
    }
}

// ----------------------------------------------------------------------------
// LayerNorm: y = y^T + x (residual), normalize over e, write [b][s][e].
// ----------------------------------------------------------------------------
__global__ __launch_bounds__(256)
void ln_kernel(const float* __restrict__ OutT, const float* __restrict__ x,
               const float* __restrict__ gamma, const float* __restrict__ beta,
               float* __restrict__ out)
{
    extern __shared__ float ys[];                 // [E_DIM][33]
    __shared__ float ps[8][NB], pq[8][NB], mu_s[NB], inv_s[NB];
    const int s = blockIdx.x, tid = threadIdx.x, lane = tid & 31, w = tid >> 5;

    #pragma unroll
    for (int bi = 0; bi < 4; bi++) {
        const int b = w * 4 + bi;
        const float* xp = x + ((size_t)b * S_DIM + s) * E_DIM;
        for (int e = lane; e < E_DIM; e += 32) ys[e * 33 + b] = xp[e];
    }
    __syncthreads();

    float sum = 0.f, sq = 0.f;
    const float* op = OutT + (size_t)s * E_DIM * NB;
    for (int e = w; e < E_DIM; e += 8) {
        float v = op[(size_t)e * NB + lane] + ys[e * 33 + lane];
        ys[e * 33 + lane] = v;
        sum += v; sq += v * v;
    }
    ps[w][lane] = sum; pq[w][lane] = sq;
    __syncthreads();

    if (tid < NB) {
        float ts = 0.f, tq = 0.f;
        #pragma unroll
        for (int i = 0; i < 8; i++) { ts += ps[i][tid]; tq += pq[i][tid]; }
        const float mu  = ts * (1.0f / E_DIM);
        const float var = tq * (1.0f / E_DIM) - mu * mu;
        mu_s[tid]  = mu;
        inv_s[tid] = rsqrtf(var + LN_EPS);
    }
    __syncthreads();

    #pragma unroll
    for (int bi = 0; bi < 4; bi++) {
        const int b = w * 4 + bi;
        const float mu = mu_s[b], inv = inv_s[b];
        float* dst = out + ((size_t)b * S_DIM + s) * E_DIM;
        for (int e = lane; e < E_DIM; e += 32)
            dst[e] = (ys[e * 33 + b] - mu) * inv * gamma[e] + beta[e];
    }
}

// ----------------------------------------------------------------------------
extern "C" void kernel_launch(void* const* d_in, const int* in_sizes, int n_in,
                              void* d_out, int out_size)
{
    const float* x     = (const float*)d_in[0];
    const float* W1    = (const float*)d_in[1];
    const float* b1    = (const float*)d_in[2];
    const float* W2    = (const float*)d_in[3];
    const float* b2    = (const float*)d_in[4];
    const float* gamma = (const float*)d_in[5];
    const float* beta  = (const float*)d_in[6];
    float* out = (float*)d_out;

    __nv_bfloat16 *hh, *hl;
    float* outt;
    cudaGetSymbolAddress((void**)&hh,   g_hh);
    cudaGetSymbolAddress((void**)&hl,   g_hl);
    cudaGetSymbolAddress((void**)&outt, g_outt);

    const int ln_smem = E_DIM * 33 * (int)sizeof(float);   // 67584 B
    cudaFuncSetAttribute(ln_kernel, cudaFuncAttributeMaxDynamicSharedMemorySize, ln_smem);
    cudaFuncSetAttribute(ffn_mma<E_DIM, F_DIM, false, false>,
                         cudaFuncAttributeMaxDynamicSharedMemorySize, SMEM_BYTES);
    cudaFuncSetAttribute(ffn_mma<F_DIM, E_DIM, true, true>,
                         cudaFuncAttributeMaxDynamicSharedMemorySize, SMEM_BYTES);

    // GEMM1: h = x @ W1 + b1 -> bf16 hi/lo scratch   (M=F, K=E)
    ffn_mma<E_DIM, F_DIM, false, false><<<dim3(F_DIM / MT, S_DIM), 256, SMEM_BYTES>>>(
        W1, x, nullptr, nullptr, b1, hh, hl, nullptr);
    // GEMM2: y^T = h @ W2 + b2 -> fp32 scratch       (M=E, K=F)
    ffn_mma<F_DIM, E_DIM, true, true><<<dim3(E_DIM / MT, S_DIM), 256, SMEM_BYTES>>>(
        W2, nullptr, hh, hl, b2, nullptr, nullptr, outt);
    // LN(+residual) -> out [b][s][e]
    ln_kernel<<<S_DIM, 256, ln_smem>>>(outt, x, gamma, beta, out);
}